// round 12
// baseline (speedup 1.0000x reference)
#include <cuda_runtime.h>
#include <cuda_fp16.h>
#include <cstdint>

// ===========================================================================
// Problem constants
// ===========================================================================
#define N_NODES 100000
#define N_EDGES 200000
#define DIM     256
#define NB      2
#define NC      8
#define TCOLS   (NB * DIM)   // 512

// Scratch (device globals: allocation-guard safe)
__device__ __half g_tf[(size_t)N_NODES * TCOLS];   // t fp16, 102.4 MB
__device__ __half g_bf[(size_t)TCOLS * DIM];       // B fp16 [n][k], n=b*256+j

// ===========================================================================
// Baseline-PTX helpers (sm_80-class only — no 'a' features!)
// ===========================================================================
__device__ __forceinline__ uint32_t smem_u32(const void* p) {
    uint32_t a;
    asm("{ .reg .u64 t; cvta.to.shared.u64 t, %1; cvt.u32.u64 %0, t; }"
        : "=r"(a) : "l"(p));
    return a;
}

#define SWZ(off) ((uint32_t)(off) ^ ((((uint32_t)(off)) >> 3) & 0x70u))

#define CP_ASYNC16(dst, src) \
    asm volatile("cp.async.cg.shared.global [%0], [%1], 16;" \
        :: "r"(dst), "l"(src) : "memory")
#define CP_COMMIT() asm volatile("cp.async.commit_group;" ::: "memory")
#define CP_WAIT(n)  asm volatile("cp.async.wait_group %0;" :: "n"(n) : "memory")

#define LDSM_X4(r0, r1, r2, r3, addr) \
    asm volatile("ldmatrix.sync.aligned.m8n8.x4.shared.b16 {%0,%1,%2,%3}, [%4];" \
        : "=r"(r0), "=r"(r1), "=r"(r2), "=r"(r3) : "r"(addr))

#define MMA_F16(c, a, b0, b1) \
    asm volatile("mma.sync.aligned.m16n8k16.row.col.f32.f16.f16.f32 " \
        "{%0,%1,%2,%3}, {%4,%5,%6,%7}, {%8,%9}, {%0,%1,%2,%3};" \
        : "+f"((c)[0]), "+f"((c)[1]), "+f"((c)[2]), "+f"((c)[3]) \
        : "r"((a)[0]), "r"((a)[1]), "r"((a)[2]), "r"((a)[3]), "r"(b0), "r"(b1))

// ===========================================================================
// Kernel 0: transpose P -> g_bf fp16, [n][k], n = b*256 + j
// ===========================================================================
__global__ __launch_bounds__(256) void prep_B(const float* __restrict__ P)
{
    int idx = blockIdx.x * blockDim.x + threadIdx.x;
    if (idx >= NB * DIM * DIM) return;
    int b = idx >> 16;
    int k = (idx >> 8) & 255;
    int j = idx & 255;
    int n = b * DIM + j;
    g_bf[(size_t)n * DIM + k] = __float2half_rn(P[idx]);
}

// ===========================================================================
// Kernel 1: fp16 mma.sync GEMM with FUSED fp32->fp16 A conversion
//   t[100000, 512] = A_fp32[100000,256] @ B^T  (B fp16 [n][k]), output fp16
// Tiles: BM=128, BN=128, BK=64. B SMEM-resident (64KB).
// A fp32 streamed via cp.async into 2x32KB stages; converted SMEM->SMEM into
// 2x16KB fp16 ping-pong buffers during the previous kc's MMA.
// 160KB SMEM -> 1 CTA/SM (register cap 255: no pressure; cp.async stays async).
// ===========================================================================
static constexpr int SM_A16   = 0;                     // 2 x 16KB
static constexpr int SM_A32   = 32768;                 // 2 x 32KB
static constexpr int SM_B     = 98304;                 // 64KB (4 panels x 16KB)
static constexpr int B_PANEL_BYTES = 16384;
static constexpr int SMEM_TOTAL = 163840;              // 160 KB

// cp.async one fp32 A stage (128 rows x 256B) into stage buf.
__device__ __forceinline__ void load_A32(uint32_t sb, int m0, int kc,
                                         int buf, int tid,
                                         const float* __restrict__ A)
{
    const uint32_t base = sb + SM_A32 + buf * 32768;
#pragma unroll
    for (int i = 0; i < 8; i++) {
        int c  = tid + i * 256;           // 0..2047 (16B chunks)
        int r  = c >> 4;                  // row 0..127
        int ck = c & 15;                  // 16B chunk in 256B row
        int gr = m0 + r;
        if (gr >= N_NODES) gr = N_NODES - 1;     // clamp (rows unused on store)
        const char* src = reinterpret_cast<const char*>(A)
                        + (size_t)gr * 1024 + kc * 256 + ck * 16;
        CP_ASYNC16(base + (uint32_t)(r * 256 + ck * 16), src);
    }
}

// Convert fp32 stage -> swizzled fp16 buffer (SMEM->SMEM).
__device__ __forceinline__ void convert_A(char* smem, int buf32, int buf16,
                                          int tid)
{
    const char* src = smem + SM_A32 + buf32 * 32768;
    char*       dst = smem + SM_A16 + buf16 * 16384;
#pragma unroll
    for (int i = 0; i < 8; i++) {
        int c  = tid + i * 256;           // 0..2047
        int r  = c >> 4;
        int ck = c & 15;
        float4 v = *reinterpret_cast<const float4*>(src + c * 16);
        __half2 h01 = __floats2half2_rn(v.x, v.y);
        __half2 h23 = __floats2half2_rn(v.z, v.w);
        uint2 packed = make_uint2(*(uint32_t*)&h01, *(uint32_t*)&h23);
        *reinterpret_cast<uint2*>(dst + SWZ((uint32_t)(r * 128 + ck * 8))) = packed;
    }
}

__global__ __launch_bounds__(256, 1) void gemm_mma(const float* __restrict__ A)
{
    extern __shared__ char smem[];
    const uint32_t sb  = smem_u32(smem);
    const uint32_t sbB = sb + SM_B;

    const int tid  = threadIdx.x;
    const int lane = tid & 31;
    const int wid  = tid >> 5;
    const int warp_m = wid & 3;       // 4 warps along M (32 rows each)
    const int warp_n = wid >> 2;      // 2 warps along N (64 cols each)
    const int m0 = blockIdx.y * 128;
    const int n0 = blockIdx.x * 128;

    // ---- prologue: group0 = B + A32(0); group1 = A32(1)
#pragma unroll
    for (int i = 0; i < 16; i++) {
        int c  = tid + i * 256;          // 0..4095
        int n  = c >> 5;                 // n row 0..127
        int ck = c & 31;                 // 16B chunk within 512B row
        int kp = ck >> 3;                // k panel 0..3
        int cb = (ck & 7) * 16;          // col byte within panel row
        size_t goff = (size_t)(n0 + n) * DIM + ck * 8;
        uint32_t soff = (uint32_t)kp * B_PANEL_BYTES + SWZ(n * 128 + cb);
        CP_ASYNC16(sbB + soff, g_bf + goff);
    }
    load_A32(sb, m0, 0, 0, tid, A);
    CP_COMMIT();
    load_A32(sb, m0, 1, 1, tid, A);
    CP_COMMIT();

    float acc[2][8][4];
#pragma unroll
    for (int t = 0; t < 2; t++)
#pragma unroll
        for (int j = 0; j < 8; j++)
#pragma unroll
            for (int q = 0; q < 4; q++) acc[t][j][q] = 0.0f;

    // ldmatrix lane address components
    const int quad  = lane >> 3;
    const int a_row = warp_m * 32 + (quad & 1) * 8 + (lane & 7);
    const int a_cb  = (quad >> 1) * 16;
    const int b_row = warp_n * 64 + (quad >> 1) * 8 + (lane & 7);
    const int b_cb  = (quad & 1) * 16;

    // convert A(0) into fp16 buf0 (needs group0 done; group1 may be pending)
    CP_WAIT(1);
    __syncthreads();
    convert_A(smem, 0, 0, tid);
    __syncthreads();

    for (int kc = 0; kc < 4; kc++) {
        // fp32 stage (kc&1) was consumed by convert before last sync; reuse it
        if (kc + 2 <= 3) {
            load_A32(sb, m0, kc + 2, (kc + 2) & 1, tid, A);
            CP_COMMIT();
        }

        const uint32_t aS = sb + SM_A16 + (uint32_t)(kc & 1) * 16384u;
        const uint32_t bS = sbB + (uint32_t)kc * B_PANEL_BYTES;

#pragma unroll
        for (int ks = 0; ks < 4; ks++) {
            uint32_t af[2][4], bf[4][4];
#pragma unroll
            for (int t = 0; t < 2; t++) {
                uint32_t off = SWZ((a_row + t * 16) * 128 + ks * 32 + a_cb);
                LDSM_X4(af[t][0], af[t][1], af[t][2], af[t][3], aS + off);
            }
#pragma unroll
            for (int j = 0; j < 4; j++) {
                uint32_t off = SWZ((b_row + j * 16) * 128 + ks * 32 + b_cb);
                LDSM_X4(bf[j][0], bf[j][1], bf[j][2], bf[j][3], bS + off);
            }
#pragma unroll
            for (int t = 0; t < 2; t++)
#pragma unroll
                for (int j = 0; j < 4; j++) {
                    MMA_F16(acc[t][2 * j],     af[t], bf[j][0], bf[j][1]);
                    MMA_F16(acc[t][2 * j + 1], af[t], bf[j][2], bf[j][3]);
                }

            // mid-kc: stage kc+1 fp32 has ~1 full kc of flight time; convert it
            // into the other fp16 buffer while this kc's MMAs keep the TC busy.
            if (ks == 1 && kc < 3) {
                if (kc < 2) { CP_WAIT(1); } else { CP_WAIT(0); }
                convert_A(smem, (kc + 1) & 1, (kc + 1) & 1, tid);
            }
        }

        // make converted buf visible to all warps; also guarantees the fp32
        // stage (kc+1)&1... consumed before next iteration's cp.async reuse
        __syncthreads();
    }

    // ---- epilogue: write t tile as fp16 to g_tf
    const int mb = m0 + warp_m * 32;
    const int nb = n0 + warp_n * 64;
    const int r0 = lane >> 2;
    const int c0 = (lane & 3) * 2;
#pragma unroll
    for (int t = 0; t < 2; t++) {
#pragma unroll
        for (int nt = 0; nt < 8; nt++) {
            int col = nb + nt * 8 + c0;
            int row = mb + t * 16 + r0;
            __half2 p01 = __floats2half2_rn(acc[t][nt][0], acc[t][nt][1]);
            __half2 p23 = __floats2half2_rn(acc[t][nt][2], acc[t][nt][3]);
            if (row < N_NODES)
                *reinterpret_cast<__half2*>(&g_tf[(size_t)row * TCOLS + col]) = p01;
            if (row + 8 < N_NODES)
                *reinterpret_cast<__half2*>(&g_tf[(size_t)(row + 8) * TCOLS + col]) = p23;
        }
    }
}

// ===========================================================================
// Kernel 2: per-edge gather + dot + combine.
// 2 edges per warp, each processed by the FULL warp (coalesced), both edges'
// loads issued up front -> 8 independent coalesced 16B loads per lane.
// ===========================================================================
__device__ __forceinline__ float dot8h(uint4 q, float4 a, float4 b)
{
    float2 f;
    float s;
    f = __half22float2(*reinterpret_cast<__half2*>(&q.x));
    s = fmaf(f.x, a.x, f.y * a.y);
    f = __half22float2(*reinterpret_cast<__half2*>(&q.y));
    s = fmaf(f.x, a.z, fmaf(f.y, a.w, s));
    f = __half22float2(*reinterpret_cast<__half2*>(&q.z));
    s = fmaf(f.x, b.x, fmaf(f.y, b.y, s));
    f = __half22float2(*reinterpret_cast<__half2*>(&q.w));
    s = fmaf(f.x, b.z, fmaf(f.y, b.w, s));
    return s;
}

__global__ __launch_bounds__(256) void edge_bilinear(
    const float* __restrict__ h_dst,
    const int*   __restrict__ u_idx,
    const int*   __restrict__ v_idx,
    const float* __restrict__ W,
    float*       __restrict__ out)
{
    const int warp = (blockIdx.x * blockDim.x + threadIdx.x) >> 5;
    const int lane = threadIdx.x & 31;
    const int e0 = warp * 2;
    const int e1 = e0 + 1;
    if (e0 >= N_EDGES) return;

    const int u0 = u_idx[e0];
    const int v0 = v_idx[e0];
    const int u1 = u_idx[e1];
    const int v1 = v_idx[e1];

    const uint4*  tu0 = reinterpret_cast<const uint4*>(g_tf + (size_t)u0 * TCOLS);
    const uint4*  tu1 = reinterpret_cast<const uint4*>(g_tf + (size_t)u1 * TCOLS);
    const float4* dv0 = reinterpret_cast<const float4*>(h_dst + (size_t)v0 * DIM);
    const float4* dv1 = reinterpret_cast<const float4*>(h_dst + (size_t)v1 * DIM);

    uint4  p0 = tu0[lane];
    uint4  p1 = tu0[lane + 32];
    float4 dA0 = dv0[2 * lane];
    float4 dB0 = dv0[2 * lane + 1];
    uint4  q0 = tu1[lane];
    uint4  q1 = tu1[lane + 32];
    float4 dA1 = dv1[2 * lane];
    float4 dB1 = dv1[2 * lane + 1];

    float s00 = dot8h(p0, dA0, dB0);
    float s01 = dot8h(p1, dA0, dB0);
    float s10 = dot8h(q0, dA1, dB1);
    float s11 = dot8h(q1, dA1, dB1);

#pragma unroll
    for (int off = 16; off > 0; off >>= 1) {
        s00 += __shfl_xor_sync(0xFFFFFFFFu, s00, off);
        s01 += __shfl_xor_sync(0xFFFFFFFFu, s01, off);
        s10 += __shfl_xor_sync(0xFFFFFFFFu, s10, off);
        s11 += __shfl_xor_sync(0xFFFFFFFFu, s11, off);
    }

    const int c = lane & 15;
    if (c < NC && (lane & 8) == 0) {
        float w0 = __ldg(W + c * NB + 0);
        float w1 = __ldg(W + c * NB + 1);
        if (lane < 16)
            out[(size_t)e0 * NC + c] = fmaf(s00, w0, s01 * w1);
        else
            out[(size_t)e1 * NC + c] = fmaf(s10, w0, s11 * w1);
    }
}

// ===========================================================================
// Launch
// ===========================================================================
extern "C" void kernel_launch(void* const* d_in, const int* in_sizes, int n_in,
                              void* d_out, int out_size)
{
    const float* h_src = (const float*)d_in[0];
    const float* h_dst = (const float*)d_in[1];
    const int*   u_idx = (const int*)d_in[2];
    const int*   v_idx = (const int*)d_in[3];
    const float* P     = (const float*)d_in[4];
    const float* W     = (const float*)d_in[5];
    float* out = (float*)d_out;

    cudaFuncSetAttribute(gemm_mma,
                         cudaFuncAttributeMaxDynamicSharedMemorySize,
                         SMEM_TOTAL);

    // 0) convert P to fp16 (transposed) — tiny
    prep_B<<<(NB * DIM * DIM + 255) / 256, 256>>>(P);

    // 1) fused-convert tensor-core node transform -> g_tf
    {
        dim3 grid(TCOLS / 128, (N_NODES + 127) / 128);
        gemm_mma<<<grid, 256, SMEM_TOTAL>>>(h_src);
    }

    // 2) edge gather + bilinear dot + combine (2 edges/warp, full-warp each)
    {
        int warps = (N_EDGES + 1) / 2;                  // 100000
        int blocks = (warps + 7) / 8;                   // 12500
        edge_bilinear<<<blocks, 256>>>(h_dst, u_idx, v_idx, W, out);
    }
}

// round 13
// speedup vs baseline: 1.3584x; 1.3584x over previous
#include <cuda_runtime.h>
#include <cuda_fp16.h>
#include <cstdint>

// ===========================================================================
// Problem constants
// ===========================================================================
#define N_NODES 100000
#define N_EDGES 200000
#define DIM     256
#define NB      2
#define NC      8
#define TCOLS   (NB * DIM)   // 512

// Scratch (device globals: allocation-guard safe)
__device__ __half g_tf[(size_t)N_NODES * TCOLS];   // t fp16, 102.4 MB
__device__ __half g_af[(size_t)N_NODES * DIM];     // A fp16 [node][k]
__device__ __half g_bf[(size_t)TCOLS * DIM];       // B fp16 [n][k], n=b*256+j

// ===========================================================================
// Baseline-PTX helpers (sm_80-class only — no 'a' features!)
// ===========================================================================
__device__ __forceinline__ uint32_t smem_u32(const void* p) {
    uint32_t a;
    asm("{ .reg .u64 t; cvta.to.shared.u64 t, %1; cvt.u32.u64 %0, t; }"
        : "=r"(a) : "l"(p));
    return a;
}

#define SWZ(off) ((uint32_t)(off) ^ ((((uint32_t)(off)) >> 3) & 0x70u))

#define CP_ASYNC16(dst, src) \
    asm volatile("cp.async.cg.shared.global [%0], [%1], 16;" \
        :: "r"(dst), "l"(src) : "memory")
#define CP_COMMIT() asm volatile("cp.async.commit_group;" ::: "memory")
#define CP_WAIT(n)  asm volatile("cp.async.wait_group %0;" :: "n"(n) : "memory")

#define LDSM_X4(r0, r1, r2, r3, addr) \
    asm volatile("ldmatrix.sync.aligned.m8n8.x4.shared.b16 {%0,%1,%2,%3}, [%4];" \
        : "=r"(r0), "=r"(r1), "=r"(r2), "=r"(r3) : "r"(addr))

#define MMA_F16(c, a, b0, b1) \
    asm volatile("mma.sync.aligned.m16n8k16.row.col.f32.f16.f16.f32 " \
        "{%0,%1,%2,%3}, {%4,%5,%6,%7}, {%8,%9}, {%0,%1,%2,%3};" \
        : "+f"((c)[0]), "+f"((c)[1]), "+f"((c)[2]), "+f"((c)[3]) \
        : "r"((a)[0]), "r"((a)[1]), "r"((a)[2]), "r"((a)[3]), "r"(b0), "r"(b1))

// ===========================================================================
// Kernel 0: fused prep, MLP=4 on the A part.
//   Blocks [0, A_BLOCKS): A fp32 -> g_af fp16, 4 independent float4/thread.
//   Blocks [A_BLOCKS, ...): P -> g_bf fp16 transposed [n][k], n = b*256+j.
// ===========================================================================
static constexpr int A_ITEMS  = N_NODES * (DIM / 4);      // 6,400,000 float4
static constexpr int A_BLOCKS = A_ITEMS / 1024;           // 6250 (exact)
static constexpr int B_ITEMS  = NB * DIM * DIM;
static constexpr int B_BLOCKS = (B_ITEMS + 255) / 256;    // 512

__global__ __launch_bounds__(256) void prep_fused(const float* __restrict__ A,
                                                  const float* __restrict__ P)
{
    if (blockIdx.x < A_BLOCKS) {
        const int base = blockIdx.x * 1024 + threadIdx.x;
        const float4* src = reinterpret_cast<const float4*>(A);
        uint2* dst = reinterpret_cast<uint2*>(g_af);
        // 4 independent loads in flight (no guards: 6.4M = 1024 * 6250)
        float4 v0 = src[base];
        float4 v1 = src[base + 256];
        float4 v2 = src[base + 512];
        float4 v3 = src[base + 768];
#define PACK_H2(v) ({ __half2 a_ = __floats2half2_rn((v).x, (v).y); \
                      __half2 b_ = __floats2half2_rn((v).z, (v).w); \
                      make_uint2(*(uint32_t*)&a_, *(uint32_t*)&b_); })
        dst[base]       = PACK_H2(v0);
        dst[base + 256] = PACK_H2(v1);
        dst[base + 512] = PACK_H2(v2);
        dst[base + 768] = PACK_H2(v3);
#undef PACK_H2
    } else {
        int idx = (blockIdx.x - A_BLOCKS) * 256 + threadIdx.x;
        if (idx >= B_ITEMS) return;
        int b = idx >> 16;
        int k = (idx >> 8) & 255;
        int j = idx & 255;
        int n = b * DIM + j;
        g_bf[(size_t)n * DIM + k] = __float2half_rn(P[idx]);
    }
}

// ===========================================================================
// Kernel 1: single-pass fp16 mma.sync GEMM  (R8 version — at HMMA floor)
//   t[100000, 512] = A[100000,256] @ B^T   (B stored [n][k]), output fp16
// Tiles: BM=128, BN=128, BK=64. B fully SMEM-resident (64KB).
// A fp16 streamed via cp.async, 3 stages (16KB each), prefetch distance 2.
// SMEM total 112KB -> 2 CTAs/SM.
// ===========================================================================
static constexpr int A_STAGE_BYTES = 16384;            // 128 rows x 128B
static constexpr int B_PANEL_BYTES = 16384;            // 128 rows x 128B
static constexpr int SM_B  = 3 * A_STAGE_BYTES;        // 49152
static constexpr int SMEM_TOTAL = SM_B + 65536;        // 114688 (112 KB)

__device__ __forceinline__ void load_A_stage(uint32_t sbA, int m0, int kc,
                                             int buf, int tid)
{
    const uint32_t base = sbA + buf * A_STAGE_BYTES;
#pragma unroll
    for (int i = 0; i < 4; i++) {
        int c  = tid + i * 256;           // 0..1023 (16B chunks)
        int r  = c >> 3;                  // row 0..127
        int ck = c & 7;                   // chunk in 128B row
        int gr = m0 + r;
        if (gr >= N_NODES) gr = N_NODES - 1;     // clamp (rows unused on store)
        size_t goff = (size_t)gr * DIM + kc * 64 + ck * 8;
        uint32_t soff = SWZ(r * 128 + ck * 16);
        CP_ASYNC16(base + soff, g_af + goff);
    }
}

__global__ __launch_bounds__(256, 2) void gemm_mma()
{
    extern __shared__ char smem[];
    const uint32_t sb   = smem_u32(smem);
    const uint32_t sbA  = sb;
    const uint32_t sbB  = sb + SM_B;

    const int tid  = threadIdx.x;
    const int lane = tid & 31;
    const int wid  = tid >> 5;
    const int warp_m = wid & 3;       // 4 warps along M (32 rows each)
    const int warp_n = wid >> 2;      // 2 warps along N (64 cols each)
    const int m0 = blockIdx.y * 128;
    const int n0 = blockIdx.x * 128;

    // ---- prologue: B (resident) + A stage 0 -> group0; A stage 1 -> group1
#pragma unroll
    for (int i = 0; i < 16; i++) {
        int c  = tid + i * 256;          // 0..4095
        int n  = c >> 5;                 // n row 0..127
        int ck = c & 31;                 // 16B chunk within 512B row
        int kp = ck >> 3;                // k panel 0..3
        int cb = (ck & 7) * 16;          // col byte within panel row
        size_t goff = (size_t)(n0 + n) * DIM + ck * 8;
        uint32_t soff = (uint32_t)kp * B_PANEL_BYTES + SWZ(n * 128 + cb);
        CP_ASYNC16(sbB + soff, g_bf + goff);
    }
    load_A_stage(sbA, m0, 0, 0, tid);
    CP_COMMIT();
    load_A_stage(sbA, m0, 1, 1, tid);
    CP_COMMIT();

    float acc[2][8][4];
#pragma unroll
    for (int t = 0; t < 2; t++)
#pragma unroll
        for (int j = 0; j < 8; j++)
#pragma unroll
            for (int q = 0; q < 4; q++) acc[t][j][q] = 0.0f;

    // ldmatrix lane address components
    const int quad  = lane >> 3;
    const int a_row = warp_m * 32 + (quad & 1) * 8 + (lane & 7);
    const int a_cb  = (quad >> 1) * 16;
    const int b_row = warp_n * 64 + (quad >> 1) * 8 + (lane & 7);
    const int b_cb  = (quad & 1) * 16;

    for (int kc = 0; kc < 4; kc++) {
        if (kc < 3) { CP_WAIT(1); } else { CP_WAIT(0); }
        __syncthreads();
        if (kc + 2 <= 3) {
            load_A_stage(sbA, m0, kc + 2, (kc + 2) % 3, tid);
            CP_COMMIT();
        }

        const uint32_t aS = sbA + (uint32_t)(kc % 3) * A_STAGE_BYTES;
        const uint32_t bS = sbB + (uint32_t)kc * B_PANEL_BYTES;

#pragma unroll
        for (int ks = 0; ks < 4; ks++) {
            uint32_t af[2][4], bf[4][4];
#pragma unroll
            for (int t = 0; t < 2; t++) {
                uint32_t off = SWZ((a_row + t * 16) * 128 + ks * 32 + a_cb);
                LDSM_X4(af[t][0], af[t][1], af[t][2], af[t][3], aS + off);
            }
#pragma unroll
            for (int j = 0; j < 4; j++) {
                uint32_t off = SWZ((b_row + j * 16) * 128 + ks * 32 + b_cb);
                LDSM_X4(bf[j][0], bf[j][1], bf[j][2], bf[j][3], bS + off);
            }
#pragma unroll
            for (int t = 0; t < 2; t++)
#pragma unroll
                for (int j = 0; j < 4; j++) {
                    MMA_F16(acc[t][2 * j],     af[t], bf[j][0], bf[j][1]);
                    MMA_F16(acc[t][2 * j + 1], af[t], bf[j][2], bf[j][3]);
                }
        }
    }

    // ---- epilogue: write t tile as fp16 to g_tf
    const int mb = m0 + warp_m * 32;
    const int nb = n0 + warp_n * 64;
    const int r0 = lane >> 2;
    const int c0 = (lane & 3) * 2;
#pragma unroll
    for (int t = 0; t < 2; t++) {
#pragma unroll
        for (int nt = 0; nt < 8; nt++) {
            int col = nb + nt * 8 + c0;
            int row = mb + t * 16 + r0;
            __half2 p01 = __floats2half2_rn(acc[t][nt][0], acc[t][nt][1]);
            __half2 p23 = __floats2half2_rn(acc[t][nt][2], acc[t][nt][3]);
            if (row < N_NODES)
                *reinterpret_cast<__half2*>(&g_tf[(size_t)row * TCOLS + col]) = p01;
            if (row + 8 < N_NODES)
                *reinterpret_cast<__half2*>(&g_tf[(size_t)(row + 8) * TCOLS + col]) = p23;
        }
    }
}

// ===========================================================================
// Kernel 2: per-edge gather + dot + combine (R8 exact — measured 49.95us)
// One warp per edge; lane covers 8 halfs of t (both bases) + 8 floats of dst.
// ===========================================================================
__global__ __launch_bounds__(256) void edge_bilinear(
    const float* __restrict__ h_dst,
    const int*   __restrict__ u_idx,
    const int*   __restrict__ v_idx,
    const float* __restrict__ W,
    float*       __restrict__ out)
{
    const int gtid = blockIdx.x * blockDim.x + threadIdx.x;
    const int e = gtid >> 5;
    const int lane = threadIdx.x & 31;
    if (e >= N_EDGES) return;

    const int u = u_idx[e];
    const int v = v_idx[e];

    const uint4*  tu4 = reinterpret_cast<const uint4*>(g_tf + (size_t)u * TCOLS);
    const float4* dv  = reinterpret_cast<const float4*>(h_dst + (size_t)v * DIM);

    // lane handles k = lane*8 .. lane*8+7 for both bases
    uint4  q0 = tu4[lane];        // basis 0: 8 halfs
    uint4  q1 = tu4[lane + 32];   // basis 1: 8 halfs (offset 256 halfs)
    float4 dA = dv[2 * lane];
    float4 dB = dv[2 * lane + 1];

    float s0, s1;
    {
        float2 f;
        f = __half22float2(*reinterpret_cast<__half2*>(&q0.x));
        s0 = fmaf(f.x, dA.x, f.y * dA.y);
        f = __half22float2(*reinterpret_cast<__half2*>(&q0.y));
        s0 = fmaf(f.x, dA.z, fmaf(f.y, dA.w, s0));
        f = __half22float2(*reinterpret_cast<__half2*>(&q0.z));
        s0 = fmaf(f.x, dB.x, fmaf(f.y, dB.y, s0));
        f = __half22float2(*reinterpret_cast<__half2*>(&q0.w));
        s0 = fmaf(f.x, dB.z, fmaf(f.y, dB.w, s0));

        f = __half22float2(*reinterpret_cast<__half2*>(&q1.x));
        s1 = fmaf(f.x, dA.x, f.y * dA.y);
        f = __half22float2(*reinterpret_cast<__half2*>(&q1.y));
        s1 = fmaf(f.x, dA.z, fmaf(f.y, dA.w, s1));
        f = __half22float2(*reinterpret_cast<__half2*>(&q1.z));
        s1 = fmaf(f.x, dB.x, fmaf(f.y, dB.y, s1));
        f = __half22float2(*reinterpret_cast<__half2*>(&q1.w));
        s1 = fmaf(f.x, dB.z, fmaf(f.y, dB.w, s1));
    }

#pragma unroll
    for (int off = 16; off > 0; off >>= 1) {
        s0 += __shfl_xor_sync(0xFFFFFFFFu, s0, off);
        s1 += __shfl_xor_sync(0xFFFFFFFFu, s1, off);
    }

    if (lane < NC) {
        float w0 = __ldg(W + lane * NB + 0);
        float w1 = __ldg(W + lane * NB + 1);
        out[(size_t)e * NC + lane] = fmaf(s0, w0, s1 * w1);
    }
}

// ===========================================================================
// Launch
// ===========================================================================
extern "C" void kernel_launch(void* const* d_in, const int* in_sizes, int n_in,
                              void* d_out, int out_size)
{
    const float* h_src = (const float*)d_in[0];
    const float* h_dst = (const float*)d_in[1];
    const int*   u_idx = (const int*)d_in[2];
    const int*   v_idx = (const int*)d_in[3];
    const float* P     = (const float*)d_in[4];
    const float* W     = (const float*)d_in[5];
    float* out = (float*)d_out;

    cudaFuncSetAttribute(gemm_mma,
                         cudaFuncAttributeMaxDynamicSharedMemorySize,
                         SMEM_TOTAL);

    // 0) fused conversion of A (MLP=4) and P to fp16
    prep_fused<<<A_BLOCKS + B_BLOCKS, 256>>>(h_src, P);

    // 1) tensor-core node transform -> g_tf  (grid: n fastest for L2 A-reuse)
    {
        dim3 grid(TCOLS / 128, (N_NODES + 127) / 128);
        gemm_mma<<<grid, 256, SMEM_TOTAL>>>();
    }

    // 2) edge gather + bilinear dot + combine (1 edge/warp, R8 mapping)
    {
        int blocks = (N_EDGES + 7) / 8;     // 8 edges per 256-thread block
        edge_bilinear<<<blocks, 256>>>(h_dst, u_idx, v_idx, W, out);
    }
}